// round 2
// baseline (speedup 1.0000x reference)
#include <cuda_runtime.h>

#define Hdim 256
#define Bdim 2048
#define Tdim 512
#define Vdim 64
#define NB   16          // batches per CTA -> 128 CTAs = 1 wave
#define NTHREADS 512     // 16 warps -> 4 per SMSP for latency hiding

// Scratch (allocation-free rule: __device__ global)
__device__ float g_WhT[Hdim * Hdim];   // WhT[k][o] = W[o, 256+k]

// ---------------------------------------------------------------------------
// Coalesced tiled transpose of Wh (one-time per replay, ~few us)
// ---------------------------------------------------------------------------
__global__ void k_transpose_Wh(const float* __restrict__ W) {
    __shared__ float tile[32][33];
    int tx = threadIdx.x, ty = threadIdx.y;
    int k0 = blockIdx.x * 32, o0 = blockIdx.y * 32;
    // read W[o][256+k], coalesced in k
    tile[ty][tx] = W[(size_t)(o0 + ty) * (2 * Hdim) + Hdim + k0 + tx];
    __syncthreads();
    // write WhT[k][o], coalesced in o
    g_WhT[(size_t)(k0 + ty) * Hdim + o0 + tx] = tile[tx][ty];
}

// ---------------------------------------------------------------------------
// Packed f32x2 helpers (ptxas never auto-fuses; must use PTX)
// ---------------------------------------------------------------------------
__device__ __forceinline__ void ffma2(unsigned long long& d,
                                      unsigned long long a,
                                      unsigned long long b) {
    asm("fma.rn.f32x2 %0, %1, %2, %0;" : "+l"(d) : "l"(a), "l"(b));
}
__device__ __forceinline__ unsigned long long pack2(float lo, float hi) {
    unsigned long long r;
    asm("mov.b64 %0, {%1, %2};" : "=l"(r) : "f"(lo), "f"(hi));
    return r;
}
__device__ __forceinline__ void unpack2(unsigned long long v, float& lo, float& hi) {
    asm("mov.b64 {%0, %1}, %2;" : "=f"(lo), "=f"(hi) : "l"(v));
}
__device__ __forceinline__ float sigmoidf(float x) {
    return __fdividef(1.0f, 1.0f + __expf(-x));
}

// ---------------------------------------------------------------------------
// Main recurrent kernel.
//
// 512 threads: oq = tid>>3 (64 output-quads of 4 outputs), bq = tid&7
// (8 batch-pairs of 2 batches). Per k: 1 LDG.128 (WhT pair-of-f32x2) +
// 1 LDS.128 (2 duplicated h values -> 2 broadcast f32x2) + 4 FFMA2.
// h duplicated in smem: hbuf[k*32 + 2b + {0,1}] = h[b][k] so LDS.128 gives
// ready f32x2 operands with zero pack MOVs.
// P table (xproj per token, bias folded) and the token block live in smem.
// ---------------------------------------------------------------------------
__global__ __launch_bounds__(NTHREADS, 1)
void k_rnn(const int* __restrict__ tokens,
           const float* __restrict__ h0,
           const float* __restrict__ emb,
           const float* __restrict__ W,
           const float* __restrict__ bias,
           float* __restrict__ out) {
    extern __shared__ char smem_raw[];
    float* h0buf = (float*)smem_raw;                 // 256*32 f = 32 KiB
    float* h1buf = h0buf + Hdim * NB * 2;            // 32 KiB
    float* Psm   = h1buf + Hdim * NB * 2;            // 64*256 f = 64 KiB
    int*   toks  = (int*)(Psm + Vdim * Hdim);        // 16*512 i = 32 KiB

    const int tid = threadIdx.x;
    const int bbase = blockIdx.x * NB;

    // ---- one-time prologue: P[v][o] = b[o] + emb[v,:]·Wx[o,:] (per-CTA) ----
    for (int idx = tid; idx < Vdim * Hdim; idx += NTHREADS) {
        int v = idx >> 8, o = idx & 255;
        const float4* e = (const float4*)(emb + (size_t)v * Hdim);
        const float4* w = (const float4*)(W + (size_t)o * (2 * Hdim));
        float acc = bias[o];
#pragma unroll 8
        for (int h = 0; h < Hdim / 4; ++h) {
            float4 ev = e[h], wv = w[h];
            acc += ev.x * wv.x + ev.y * wv.y + ev.z * wv.z + ev.w * wv.w;
        }
        Psm[idx] = acc;
    }
    // ---- stage this CTA's token block ----
    for (int idx = tid; idx < NB * Tdim; idx += NTHREADS) {
        int b = idx >> 9, t = idx & 511;
        toks[idx] = tokens[(size_t)(bbase + b) * Tdim + t];
    }
    // ---- init h (duplicated) ----
    for (int i = tid; i < Hdim * NB; i += NTHREADS) {
        int k = i >> 4, b = i & 15;
        float v = h0[(size_t)(bbase + b) * Hdim + k];
        h0buf[k * 32 + 2 * b]     = v;
        h0buf[k * 32 + 2 * b + 1] = v;
    }
    __syncthreads();

    float* hcur = h0buf;
    float* hnxt = h1buf;
    const int oq = tid >> 3;          // 0..63
    const int bq = tid & 7;           // 0..7
    const int o0 = oq * 4;
    const int bl0 = bq * 2;           // local batches bl0, bl0+1

    for (int t = 0; t < Tdim; ++t) {
        // ---- accumulators <- xproj (bias folded into P) ----
        int tok0 = toks[bl0 * Tdim + t];
        int tok1 = toks[(bl0 + 1) * Tdim + t];
        float4 p0 = *(const float4*)&Psm[tok0 * Hdim + o0];
        float4 p1 = *(const float4*)&Psm[tok1 * Hdim + o0];
        unsigned long long a00 = pack2(p0.x, p0.y), a10 = pack2(p0.z, p0.w);
        unsigned long long a01 = pack2(p1.x, p1.y), a11 = pack2(p1.z, p1.w);

        // ---- recurrent GEMV: acc += h @ Wh^T ----
        const float* hr = hcur + 4 * bq;
        const float* wp = g_WhT + o0;
#pragma unroll 8
        for (int k = 0; k < Hdim; ++k) {
            ulonglong2 w2 = *(const ulonglong2*)(wp + (size_t)k * Hdim);
            ulonglong2 hA = *(const ulonglong2*)(hr + k * 32);
            ffma2(a00, w2.x, hA.x);   // outputs (o0,o0+1), batch bl0
            ffma2(a10, w2.y, hA.x);   // outputs (o0+2,o0+3), batch bl0
            ffma2(a01, w2.x, hA.y);   // batch bl0+1
            ffma2(a11, w2.y, hA.y);
        }

        // ---- sigmoid, store output, stage duplicated h_{t+1} ----
        float x0, x1, x2, x3;
        unpack2(a00, x0, x1); unpack2(a10, x2, x3);
        float4 s0;
        s0.x = sigmoidf(x0); s0.y = sigmoidf(x1);
        s0.z = sigmoidf(x2); s0.w = sigmoidf(x3);
        unpack2(a01, x0, x1); unpack2(a11, x2, x3);
        float4 s1;
        s1.x = sigmoidf(x0); s1.y = sigmoidf(x1);
        s1.z = sigmoidf(x2); s1.w = sigmoidf(x3);

        float* outp = out + (size_t)t * (Bdim * Hdim);
        *(float4*)&outp[(size_t)(bbase + bl0) * Hdim + o0]     = s0;
        *(float4*)&outp[(size_t)(bbase + bl0 + 1) * Hdim + o0] = s1;

        *(unsigned long long*)&hnxt[(o0 + 0) * 32 + 2 * bl0]       = pack2(s0.x, s0.x);
        *(unsigned long long*)&hnxt[(o0 + 1) * 32 + 2 * bl0]       = pack2(s0.y, s0.y);
        *(unsigned long long*)&hnxt[(o0 + 2) * 32 + 2 * bl0]       = pack2(s0.z, s0.z);
        *(unsigned long long*)&hnxt[(o0 + 3) * 32 + 2 * bl0]       = pack2(s0.w, s0.w);
        *(unsigned long long*)&hnxt[(o0 + 0) * 32 + 2 * (bl0 + 1)] = pack2(s1.x, s1.x);
        *(unsigned long long*)&hnxt[(o0 + 1) * 32 + 2 * (bl0 + 1)] = pack2(s1.y, s1.y);
        *(unsigned long long*)&hnxt[(o0 + 2) * 32 + 2 * (bl0 + 1)] = pack2(s1.z, s1.z);
        *(unsigned long long*)&hnxt[(o0 + 3) * 32 + 2 * (bl0 + 1)] = pack2(s1.w, s1.w);

        __syncthreads();
        float* tmp = hcur; hcur = hnxt; hnxt = tmp;
    }
}

// ---------------------------------------------------------------------------
// Harness entry
// Inputs: tokens(i32 2048x512), h0(f32 2048x256), emb(f32 64x256),
//         W(f32 256x512), b(f32 256).  Output: f32 (512,2048,256)
// ---------------------------------------------------------------------------
extern "C" void kernel_launch(void* const* d_in, const int* in_sizes, int n_in,
                              void* d_out, int out_size) {
    const int*   tokens = (const int*)d_in[0];
    const float* h0     = (const float*)d_in[1];
    const float* emb    = (const float*)d_in[2];
    const float* W      = (const float*)d_in[3];
    const float* bias   = (const float*)d_in[4];
    float*       out    = (float*)d_out;
    (void)in_sizes; (void)n_in; (void)out_size;

    dim3 tb(32, 32);
    dim3 tg(Hdim / 32, Hdim / 32);
    k_transpose_Wh<<<tg, tb>>>(W);

    const int smem_bytes = (2 * Hdim * NB * 2 + Vdim * Hdim) * (int)sizeof(float)
                         + NB * Tdim * (int)sizeof(int);      // 160 KiB
    cudaFuncSetAttribute(k_rnn, cudaFuncAttributeMaxDynamicSharedMemorySize, smem_bytes);
    k_rnn<<<Bdim / NB, NTHREADS, smem_bytes>>>(tokens, h0, emb, W, bias, out);
}

// round 4
// speedup vs baseline: 13.3281x; 13.3281x over previous
#include <cuda_runtime.h>
#include <cuda_fp16.h>
#include <cstdint>

#define Hdim 256
#define Bdim 2048
#define Tdim 512
#define Vdim 64
#define NB   16          // batches per CTA -> 128 CTAs
#define NTH  256         // 8 warps
#define HROW 24          // padded hT row stride in halfs (48B) -> conflict-free ldmatrix

// ---- shared memory layout (bytes) ----
#define SM_P     0         // P[64][256] f32 (xproj per token, bias folded): 64 KiB
#define SM_H0    65536     // hT buf0: 256 rows x 24 halfs = 12288 B
#define SM_H1    77824     // hT buf1: 12288 B
#define SM_TOK   90112     // 16 ints
#define SM_STAGE 90368     // prologue scratch: embT f32 (64KiB) then Whh fp16 (128KiB)
#define SMEM_TOTAL (90368 + 131072)   // 221440 B

// ---------------------------------------------------------------------------
__device__ __forceinline__ uint32_t smem_u32(const void* p) {
    uint32_t a;
    asm("{ .reg .u64 t; cvta.to.shared.u64 t, %1; cvt.u32.u64 %0, t; }"
        : "=r"(a) : "l"(p));
    return a;
}
__device__ __forceinline__ float sigmoidf(float x) {
    return __fdividef(1.0f, 1.0f + __expf(-x));
}
__device__ __forceinline__ void ffma2(unsigned long long& d,
                                      unsigned long long a, unsigned long long b) {
    asm("fma.rn.f32x2 %0, %1, %2, %0;" : "+l"(d) : "l"(a), "l"(b));
}
__device__ __forceinline__ unsigned long long pack2(float lo, float hi) {
    unsigned long long r;
    asm("mov.b64 %0, {%1, %2};" : "=l"(r) : "f"(lo), "f"(hi));
    return r;
}
// m16n8k16 row.col f32 = f16*f16 + f32
__device__ __forceinline__ void mma16816(float* d, const uint32_t* a,
                                         uint32_t b0, uint32_t b1) {
    asm volatile(
        "mma.sync.aligned.m16n8k16.row.col.f32.f16.f16.f32 "
        "{%0,%1,%2,%3}, {%4,%5,%6,%7}, {%8,%9}, {%0,%1,%2,%3};"
        : "+f"(d[0]), "+f"(d[1]), "+f"(d[2]), "+f"(d[3])
        : "r"(a[0]), "r"(a[1]), "r"(a[2]), "r"(a[3]), "r"(b0), "r"(b1));
}
__device__ __forceinline__ void ldmx4t(uint32_t& r0, uint32_t& r1,
                                       uint32_t& r2, uint32_t& r3, uint32_t addr) {
    asm volatile(
        "ldmatrix.sync.aligned.m8n8.x4.trans.shared.b16 {%0,%1,%2,%3}, [%4];"
        : "=r"(r0), "=r"(r1), "=r"(r2), "=r"(r3) : "r"(addr));
}

// ---------------------------------------------------------------------------
// Persistent RNN: one CTA owns 16 batch chains for all 512 steps.
// Warp w computes output rows [32w, 32w+32) as 2 m-tiles of m16n8k16 HMMA.
// Wh fragments (fp16) are register-resident for the whole kernel.
// ---------------------------------------------------------------------------
__global__ __launch_bounds__(NTH, 1)
void k_rnn(const int* __restrict__ tokens,
           const float* __restrict__ h0,
           const float* __restrict__ emb,
           const float* __restrict__ W,
           const float* __restrict__ bias,
           float* __restrict__ out) {
    extern __shared__ char smem[];
    const uint32_t sbase = smem_u32(smem);
    float* Psm  = (float*)(smem + SM_P);
    int*   toks = (int*)(smem + SM_TOK);

    const int tid  = threadIdx.x;
    const int wid  = tid >> 5;
    const int lane = tid & 31;
    const int g    = lane >> 2;     // group id 0..7
    const int r    = lane & 3;      // thread-in-group 0..3
    const int bbase = blockIdx.x * NB;

    // ============== Prologue ==============
    // (1) embT[k][v] staged in SM_STAGE (f32)
    {
        float* embT = (float*)(smem + SM_STAGE);
        for (int idx = tid; idx < Vdim * Hdim; idx += NTH) {
            int k = idx >> 6, v = idx & 63;
            embT[idx] = emb[(size_t)v * Hdim + k];
        }
    }
    __syncthreads();
    // (2) P[v][o] = bias[o] + emb[v,:]·Wx[o,:]  (thread owns column o = tid)
    {
        const float* embT = (const float*)(smem + SM_STAGE);
        const int o = tid;
        const float bo = bias[o];
        const float4* wrow = (const float4*)(W + (size_t)o * (2 * Hdim));
        for (int vg = 0; vg < 4; ++vg) {
            unsigned long long acc[8];
#pragma unroll
            for (int i = 0; i < 8; ++i) acc[i] = pack2(0.f, 0.f);
            for (int k4 = 0; k4 < Hdim / 4; ++k4) {
                float4 wv = wrow[k4];
#pragma unroll
                for (int kk = 0; kk < 4; ++kk) {
                    int k = k4 * 4 + kk;
                    float w = (kk == 0) ? wv.x : (kk == 1) ? wv.y : (kk == 2) ? wv.z : wv.w;
                    unsigned long long wpair = pack2(w, w);
                    const ulonglong2* ep =
                        (const ulonglong2*)(embT + (size_t)k * 64 + vg * 16);
                    ulonglong2 e0 = ep[0], e1 = ep[1], e2 = ep[2], e3 = ep[3];
                    ffma2(acc[0], wpair, e0.x); ffma2(acc[1], wpair, e0.y);
                    ffma2(acc[2], wpair, e1.x); ffma2(acc[3], wpair, e1.y);
                    ffma2(acc[4], wpair, e2.x); ffma2(acc[5], wpair, e2.y);
                    ffma2(acc[6], wpair, e3.x); ffma2(acc[7], wpair, e3.y);
                }
            }
#pragma unroll
            for (int i = 0; i < 8; ++i) {
                float lo = __uint_as_float((uint32_t)(acc[i] & 0xffffffffu));
                float hi = __uint_as_float((uint32_t)(acc[i] >> 32));
                int v0 = vg * 16 + 2 * i;
                Psm[(size_t)v0 * Hdim + o]       = bo + lo;
                Psm[(size_t)(v0 + 1) * Hdim + o] = bo + hi;
            }
        }
    }
    __syncthreads();
    // (3) stage Wh as fp16 [o][k] (k contiguous) into SM_STAGE
    {
        __half* Whh = (__half*)(smem + SM_STAGE);
        for (int idx = tid; idx < Hdim * Hdim; idx += NTH) {
            int o = idx >> 8, k = idx & 255;
            Whh[(size_t)o * Hdim + k] =
                __float2half_rn(W[(size_t)o * (2 * Hdim) + Hdim + k]);
        }
    }
    __syncthreads();
    // (4) build register-resident A fragments: afrag[mi][c][0..3]
    uint32_t afrag[2][16][4];
    {
        const __half* Whh = (const __half*)(smem + SM_STAGE);
#pragma unroll
        for (int mi = 0; mi < 2; ++mi) {
            int row0 = wid * 32 + mi * 16 + g;
            int row1 = row0 + 8;
#pragma unroll
            for (int c = 0; c < 16; ++c) {
                int k0 = c * 16 + r * 2;
                afrag[mi][c][0] = *(const uint32_t*)&Whh[(size_t)row0 * Hdim + k0];
                afrag[mi][c][1] = *(const uint32_t*)&Whh[(size_t)row1 * Hdim + k0];
                afrag[mi][c][2] = *(const uint32_t*)&Whh[(size_t)row0 * Hdim + k0 + 8];
                afrag[mi][c][3] = *(const uint32_t*)&Whh[(size_t)row1 * Hdim + k0 + 8];
            }
        }
    }
    // (5) init hT buf0 from h0 (fp16, padded rows)
    {
        __half* hT0 = (__half*)(smem + SM_H0);
        for (int idx = tid; idx < NB * Hdim; idx += NTH) {
            int b = idx >> 8, k = idx & 255;
            hT0[(size_t)k * HROW + b] =
                __float2half_rn(h0[(size_t)(bbase + b) * Hdim + k]);
        }
    }
    __syncthreads();

    // ldmatrix per-lane row address offset (within a buffer):
    // matrices: m0=k[0:8)/n0, m1=k[8:16)/n0, m2=k[0:8)/n8, m3=k[8:16)/n8
    const int klocal = lane & 7;
    const int sel    = lane >> 3;
    const uint32_t ldm_off =
        (uint32_t)(((sel & 1) * 8 + klocal) * (HROW * 2) + ((sel >> 1) * 8) * 2);

    // epilogue constants
    const int o0m[2] = { wid * 32 + g, wid * 32 + 16 + g };   // rows for mi=0,1 (low)
    float* const outbase = out + (size_t)bbase * Hdim;

    // ============== Recurrent loop ==============
    for (int t = 0; t < Tdim; ++t) {
        // prefetch this step's tokens (latency hidden under MMA)
        int mytok = 0;
        if (tid < NB) mytok = tokens[(size_t)(bbase + tid) * Tdim + t];

        const uint32_t rbuf = sbase + ((t & 1) ? SM_H1 : SM_H0) + ldm_off;

        float d[2][2][4];
#pragma unroll
        for (int mi = 0; mi < 2; ++mi)
#pragma unroll
            for (int ni = 0; ni < 2; ++ni)
#pragma unroll
                for (int i = 0; i < 4; ++i) d[mi][ni][i] = 0.0f;

#pragma unroll
        for (int c = 0; c < 16; ++c) {
            uint32_t b0, b1, b2, b3;
            ldmx4t(b0, b1, b2, b3, rbuf + (uint32_t)c * (16 * HROW * 2));
            mma16816(d[0][0], afrag[0][c], b0, b1);
            mma16816(d[0][1], afrag[0][c], b2, b3);
            mma16816(d[1][0], afrag[1][c], b0, b1);
            mma16816(d[1][1], afrag[1][c], b2, b3);
        }

        if (tid < NB) toks[tid] = mytok;
        __syncthreads();

        // epilogue: x = D + P[token][o]; h' = sigmoid(x); store out + hT_next
        __half* wT = (__half*)(smem + ((t & 1) ? SM_H0 : SM_H1));
        float* outp = outbase + (size_t)t * (Bdim * Hdim);
        int tk[4];
#pragma unroll
        for (int ni = 0; ni < 2; ++ni) {
            tk[2 * ni]     = toks[ni * 8 + 2 * r];
            tk[2 * ni + 1] = toks[ni * 8 + 2 * r + 1];
        }
#pragma unroll
        for (int mi = 0; mi < 2; ++mi) {
            int o_lo = o0m[mi], o_hi = o0m[mi] + 8;
#pragma unroll
            for (int ni = 0; ni < 2; ++ni) {
                int bcol = ni * 8 + 2 * r;
                float s00 = sigmoidf(d[mi][ni][0] + Psm[(size_t)tk[2*ni]   * Hdim + o_lo]);
                float s01 = sigmoidf(d[mi][ni][1] + Psm[(size_t)tk[2*ni+1] * Hdim + o_lo]);
                float s10 = sigmoidf(d[mi][ni][2] + Psm[(size_t)tk[2*ni]   * Hdim + o_hi]);
                float s11 = sigmoidf(d[mi][ni][3] + Psm[(size_t)tk[2*ni+1] * Hdim + o_hi]);
                outp[(size_t)bcol       * Hdim + o_lo] = s00;
                outp[(size_t)(bcol + 1) * Hdim + o_lo] = s01;
                outp[(size_t)bcol       * Hdim + o_hi] = s10;
                outp[(size_t)(bcol + 1) * Hdim + o_hi] = s11;
                // h' fp16: two halfs (b, b+1) share one 32-bit word -> conflict-free STS.32
                *(__half2*)&wT[(size_t)o_lo * HROW + bcol] =
                    __floats2half2_rn(s00, s01);
                *(__half2*)&wT[(size_t)o_hi * HROW + bcol] =
                    __floats2half2_rn(s10, s11);
            }
        }
        __syncthreads();
    }
}

// ---------------------------------------------------------------------------
// Harness entry.
// Inputs: tokens(i32 2048x512), h0(f32 2048x256), emb(f32 64x256),
//         W(f32 256x512), b(f32 256).  Output: f32 (512,2048,256)
// ---------------------------------------------------------------------------
extern "C" void kernel_launch(void* const* d_in, const int* in_sizes, int n_in,
                              void* d_out, int out_size) {
    const int*   tokens = (const int*)d_in[0];
    const float* h0     = (const float*)d_in[1];
    const float* emb    = (const float*)d_in[2];
    const float* W      = (const float*)d_in[3];
    const float* bias   = (const float*)d_in[4];
    float*       out    = (float*)d_out;
    (void)in_sizes; (void)n_in; (void)out_size;

    cudaFuncSetAttribute(k_rnn, cudaFuncAttributeMaxDynamicSharedMemorySize, SMEM_TOTAL);
    k_rnn<<<Bdim / NB, NTH, SMEM_TOTAL>>>(tokens, h0, emb, W, bias, out);
}